// round 8
// baseline (speedup 1.0000x reference)
#include <cuda_runtime.h>

// HiPoNet collapse: P = 0.5*(Wm/colsum) + 0.5*I is column-stochastic, so
// 1^T P^t = 1^T and mean_n(P^t X) = mean_n(X) exactly. Output:
//   out[b, w*160 + k*32 + d] = mean_n(pc[b,n,d]) * alphas[w,d], k=0..4.
//
// R8: row partition (full 128B lines -> 512 L1tex wavefronts/SM instead of
// 2048 for the sector partition) + one-directional flag combining:
// per batch, ranks 1..3 store a 32-float partial, release-flag, and exit;
// rank 0 spin-polls the 3 flags (volatile = L1-bypass), sums, and writes
// all 640 outputs. No barriers, no atomics, no clusters.

#define NPTS   2048
#define DIM    32
#define NW     4
#define NCOLL  5
#define FOUT   (NW * NCOLL * DIM)        // 640 per batch
#define RQ     4                         // row quarters per batch
#define BLK    512
#define ROWS   (NPTS / RQ)               // 512 rows per block
#define QPR    (DIM / 4)                 // 8 float4 per row
#define LPT    8                         // loads per thread

__device__ float                 g_part[4][RQ][DIM];   // partial column sums
__device__ volatile unsigned int g_flag[4][RQ];        // zero-init; self-reset

__device__ __forceinline__ float4 f4add(float4 a, float4 b) {
    return make_float4(a.x + b.x, a.y + b.y, a.z + b.z, a.w + b.w);
}

__global__ __launch_bounds__(BLK, 1)
void hiponet_kernel(const float* __restrict__ pc,
                    const float* __restrict__ alphas,
                    float* __restrict__ out)
{
    const int b  = blockIdx.x >> 2;      // batch 0..3
    const int r4 = blockIdx.x & 3;       // row quarter 0..3
    const int t  = threadIdx.x;          // 0..511
    const int q  = t & (QPR - 1);        // float4 slot in row, 0..7
    const int rg = t >> 3;               // row group, 0..63

    __shared__ float  sm[16][DIM];       // per-warp partials
    __shared__ float  part_s[DIM];
    __shared__ float  al[NW * DIM];

    if (r4 == 0 && t < NW * DIM) al[t] = alphas[t];   // consumer prefetch

    // ---- phase 1: 512 full rows, 8 independent LDG.128 per thread ----
    const float4* __restrict__ base =
        (const float4*)(pc + ((size_t)b * NPTS + r4 * ROWS) * DIM);

    float4 v[LPT];
    #pragma unroll
    for (int k = 0; k < LPT; ++k)
        v[k] = base[(size_t)(rg + (k << 6)) * QPR + q];
    float4 s = f4add(f4add(f4add(v[0], v[1]), f4add(v[2], v[3])),
                     f4add(f4add(v[4], v[5]), f4add(v[6], v[7])));

    // warp reduce across the 4 row-groups in this warp (lane bit 3,4 = rg)
    #pragma unroll
    for (int m = 8; m <= 16; m <<= 1) {
        s.x += __shfl_xor_sync(0xffffffffu, s.x, m);
        s.y += __shfl_xor_sync(0xffffffffu, s.y, m);
        s.z += __shfl_xor_sync(0xffffffffu, s.z, m);
        s.w += __shfl_xor_sync(0xffffffffu, s.w, m);
    }
    if ((t & 31) < QPR)                  // lanes 0..7 hold warp's 32-row sums
        *(float4*)&sm[t >> 5][q * 4] = s;
    __syncthreads();

    if (t < DIM) {                       // d = t: sum 16 warp partials
        float acc = 0.f;
        #pragma unroll
        for (int i = 0; i < 16; ++i) acc += sm[i][t];
        part_s[t] = acc;
    }
    __syncthreads();

    if (r4 != 0) {
        // ---- producer: publish partial + release flag, exit ----
        if (t < DIM) g_part[b][r4][t] = part_s[t];
        __syncthreads();
        if (t == 0) {
            __threadfence();             // partial stores before flag
            g_flag[b][r4] = 1u;
        }
        return;
    }

    // ---- consumer (rank 0): wait for the 3 producers ----
    if (t < RQ - 1) {
        while (g_flag[b][t + 1] == 0u) { }   // volatile: bypasses L1
    }
    __syncthreads();

    __shared__ float mean_s[DIM];
    if (t < DIM) {
        // volatile scalar loads: L1-bypass, sees producers' L2 data
        volatile const float* gp = &g_part[b][0][0];
        float acc = part_s[t]
                  + gp[1 * DIM + t] + gp[2 * DIM + t] + gp[3 * DIM + t];
        mean_s[t] = acc * (1.0f / (float)NPTS);
    }
    __syncthreads();
    if (t < RQ - 1) g_flag[b][t + 1] = 0u;   // reset for next graph replay

    // ---- write this batch's 640 outputs ----
    #pragma unroll
    for (int i = t; i < FOUT; i += BLK) {
        const int w = i / (NCOLL * DIM);
        const int d = i & 31;
        out[b * FOUT + i] = mean_s[d] * al[w * DIM + d];
    }
}

extern "C" void kernel_launch(void* const* d_in, const int* in_sizes, int n_in,
                              void* d_out, int out_size)
{
    const float* pc     = (const float*)d_in[0];  // [4, 2048, 32] fp32
    // d_in[1] = sigma: output is invariant to the diffusion operator
    const float* alphas = (const float*)d_in[2];  // [4, 32] fp32
    float* out = (float*)d_out;                   // [4, 640] fp32

    hiponet_kernel<<<16, BLK>>>(pc, alphas, out);
}

// round 9
// speedup vs baseline: 1.1163x; 1.1163x over previous
#include <cuda_runtime.h>

// HiPoNet collapse: P = 0.5*(Wm/colsum) + 0.5*I is column-stochastic, so
// 1^T P^t = 1^T and mean_n(P^t X) = mean_n(X) exactly. Output:
//   out[b, w*160 + k*32 + d] = mean_n(pc[b,n,d]) * alphas[w,d], k=0..4.
//
// R9: zero-communication sector partition (best measured structure; all
// three cross-CTA combining schemes -- L2 atomics, cluster barriers,
// producer/consumer flags -- measured slower). Grid=16 = (batch b,
// dim-quarter dq). 256 threads/block, 16 independent LDG.128/thread
// (same warp-LDG count as R7 but 8 warps: shorter barrier/tail skew).

#define NPTS   2048
#define DIM    32
#define NW     4
#define NCOLL  5
#define FOUT   (NW * NCOLL * DIM)        // 640 per batch
#define BLK    256
#define DQ     8                         // dims per block (one 32B sector)
#define RPP    (BLK / 2)                 // 128 rows per pass
#define LPT    (NPTS / RPP)              // 16 loads per thread
#define NWARP  (BLK / 32)                // 8 warps

__device__ __forceinline__ float4 f4add(float4 a, float4 b) {
    return make_float4(a.x + b.x, a.y + b.y, a.z + b.z, a.w + b.w);
}

__device__ __forceinline__ float4 f4shfl_xor(float4 v, int m) {
    v.x += __shfl_xor_sync(0xffffffffu, v.x, m);
    v.y += __shfl_xor_sync(0xffffffffu, v.y, m);
    v.z += __shfl_xor_sync(0xffffffffu, v.z, m);
    v.w += __shfl_xor_sync(0xffffffffu, v.w, m);
    return v;
}

__global__ __launch_bounds__(BLK, 1)
void hiponet_kernel(const float* __restrict__ pc,
                    const float* __restrict__ alphas,
                    float* __restrict__ out)
{
    const int b    = blockIdx.x >> 2;    // batch 0..3
    const int dq   = blockIdx.x & 3;     // dim quarter 0..3
    const int t    = threadIdx.x;        // 0..255
    const int half = t & 1;              // which float4 of the 32B sector
    const int r    = t >> 1;             // row lane 0..127

    __shared__ float sm[NWARP][DQ];      // per-warp partials
    __shared__ float mean_s[DQ];
    __shared__ float al[NW * DQ];

    // alphas prefetch for this dim quarter (overlaps DRAM latency)
    if (t < NW * DQ)
        al[t] = alphas[(t >> 3) * DIM + dq * DQ + (t & 7)];

    // ---- 16 independent LDG.128 per thread over the block's sector ----
    const float4* __restrict__ base =
        (const float4*)pc + ((size_t)b * NPTS + r) * (DIM / 4) + dq * 2 + half;

    float4 v[LPT];
    #pragma unroll
    for (int k = 0; k < LPT; ++k)
        v[k] = base[(size_t)k * RPP * (DIM / 4)];

    float4 s0 = f4add(f4add(f4add(v[0],  v[1]),  f4add(v[2],  v[3])),
                      f4add(f4add(v[4],  v[5]),  f4add(v[6],  v[7])));
    float4 s1 = f4add(f4add(f4add(v[8],  v[9]),  f4add(v[10], v[11])),
                      f4add(f4add(v[12], v[13]), f4add(v[14], v[15])));
    float4 s = f4add(s0, s1);

    // ---- butterfly over row lanes (parity bit 0 = half stays fixed) ----
    s = f4shfl_xor(s, 2);
    s = f4shfl_xor(s, 4);
    s = f4shfl_xor(s, 8);
    s = f4shfl_xor(s, 16);
    // lanes 0 (half 0) and 1 (half 1) hold this warp's 256-row sums

    if ((t & 31) < 2)
        *(float4*)&sm[t >> 5][half * 4] = s;
    __syncthreads();

    if (t < DQ) {                        // dl = t: sum 8 warp partials
        float acc = (sm[0][t] + sm[1][t]) + (sm[2][t] + sm[3][t])
                  + (sm[4][t] + sm[5][t]) + (sm[6][t] + sm[7][t]);
        mean_s[t] = acc * (1.0f / (float)NPTS);
    }
    __syncthreads();

    // ---- write this block's disjoint 160 outputs ----
    if (t < NW * NCOLL * DQ) {           // 160
        const int ww  = t / (NCOLL * DQ);
        const int rem = t - ww * (NCOLL * DQ);
        const int kk  = rem >> 3;
        const int dl  = rem & 7;
        out[b * FOUT + ww * (NCOLL * DIM) + kk * DIM + dq * DQ + dl] =
            mean_s[dl] * al[ww * DQ + dl];
    }
}

extern "C" void kernel_launch(void* const* d_in, const int* in_sizes, int n_in,
                              void* d_out, int out_size)
{
    const float* pc     = (const float*)d_in[0];  // [4, 2048, 32] fp32
    // d_in[1] = sigma: output is invariant to the diffusion operator
    const float* alphas = (const float*)d_in[2];  // [4, 32] fp32
    float* out = (float*)d_out;                   // [4, 640] fp32

    hiponet_kernel<<<16, BLK>>>(pc, alphas, out);
}